// round 16
// baseline (speedup 1.0000x reference)
#include <cuda_runtime.h>
#include <cuda_bf16.h>
#include <cuda_fp16.h>
#include <math.h>
#include <stdint.h>

// ---------------- static config ----------------
#define Bv 4
#define Lv 4096
#define Dv 1024
#define Kv 32
#define Hv 32
#define Av 4
#define CKv 4
#define DIv 1024          // d_inner
#define ZCv 2080          // 2*DI + K
#define BLv (Bv*Lv)       // 16384
#define NPAD1 2304        // 9 * 256 (padded N for GEMM1, N-tile 256)

#define NSEG 512
#define SEGLEN (Lv/NSEG)  // 8

// ---------------- scratch (device globals; no allocation) ----------------
__device__ float g_z[(size_t)BLv * ZCv];        // in_proj output
__device__ float g_merged[(size_t)BLv * ZCv];   // [den|re|im] features
__device__ float g_gate[(size_t)BLv * DIv];     // silu gate
__device__ __half g_hh[(size_t)BLv * DIv];      // y * gate (fp16, GEMM2 A)
__device__ float g_part[Bv][NSEG][ZCv];         // segment partial sums
// fp16 activations for GEMM1
__device__ __half g_xh[(size_t)BLv * Dv];
// transposed fp16 weights, K-major (single-rounded; 1-term GEMM)
__device__ __half g_ch1[(size_t)NPAD1 * Dv];    // W_in
__device__ __half g_ch2[(size_t)Dv * Dv];       // W_out

// ---------------- helpers ----------------
__device__ __forceinline__ uint32_t smem_u32(const void* p) {
    uint32_t a;
    asm("{ .reg .u64 t; cvta.to.shared.u64 t, %1; cvt.u32.u64 %0, t; }" : "=r"(a) : "l"(p));
    return a;
}
#define CP_ASYNC_16(dst_u32, src_ptr) \
    asm volatile("cp.async.cg.shared.global [%0], [%1], 16;" :: "r"(dst_u32), "l"(src_ptr))
#define CP_ASYNC_COMMIT() asm volatile("cp.async.commit_group;" ::: "memory")
#define CP_ASYNC_WAIT0()  asm volatile("cp.async.wait_group 0;" ::: "memory")

#define LDMX4(r, addr) \
    asm volatile("ldmatrix.sync.aligned.m8n8.x4.shared.b16 {%0,%1,%2,%3}, [%4];" \
        : "=r"((r)[0]), "=r"((r)[1]), "=r"((r)[2]), "=r"((r)[3]) : "r"(addr))

__device__ __forceinline__ void mma_fp16(float c[4], const uint32_t a[4],
                                         uint32_t b0, uint32_t b1) {
    asm volatile(
        "mma.sync.aligned.m16n8k16.row.col.f32.f16.f16.f32 "
        "{%0,%1,%2,%3}, {%4,%5,%6,%7}, {%8,%9}, {%0,%1,%2,%3};"
        : "+f"(c[0]), "+f"(c[1]), "+f"(c[2]), "+f"(c[3])
        : "r"(a[0]), "r"(a[1]), "r"(a[2]), "r"(a[3]), "r"(b0), "r"(b1));
}

// ---------------- weight transpose (fp16, single-rounded) ----------------
__global__ void prep_h(const float* __restrict__ W,
                       __half* __restrict__ Bh,
                       int Kdim, int Nreal) {
    __shared__ float t[32][33];
    const int nb = blockIdx.x * 32, kb = blockIdx.y * 32;
    const int tx = threadIdx.x, ty = threadIdx.y;   // 32 x 8
    #pragma unroll
    for (int j = 0; j < 4; j++) {
        int k = kb + ty + j * 8, n = nb + tx;
        t[ty + j * 8][tx] = (n < Nreal) ? W[(size_t)k * Nreal + n] : 0.f;
    }
    __syncthreads();
    #pragma unroll
    for (int j = 0; j < 4; j++) {
        int n = nb + ty + j * 8, k = kb + tx;
        Bh[(size_t)n * Kdim + k] = __float2half_rn(t[tx][ty + j * 8]);
    }
}

// ---------------- x fp32 -> fp16 (single-rounded) ----------------
__global__ __launch_bounds__(256) void split_x(const float* __restrict__ x) {
    size_t i = ((size_t)blockIdx.x * 256 + threadIdx.x) * 4;
    float4 v = *(const float4*)(x + i);
    uint32_t hh[2];
    hh[0] = (uint32_t)__half_as_ushort(__float2half_rn(v.x))
          | ((uint32_t)__half_as_ushort(__float2half_rn(v.y)) << 16);
    hh[1] = (uint32_t)__half_as_ushort(__float2half_rn(v.z))
          | ((uint32_t)__half_as_ushort(__float2half_rn(v.w)) << 16);
    *(uint2*)(g_xh + i) = make_uint2(hh[0], hh[1]);
}

// ---------------- GEMM (1-term fp16; 512 thr, warp 32x64, BK=128) ----------------
// Row = 256B data + 16B pad = 272B: 68-word stride keeps ldmatrix phases conflict-free.
#define ROWB   272
#define ATI    (128 * ROWB)            // 34816
#define BTI    (256 * ROWB)            // 69632
#define STG1   (ATI + BTI)             // 104448: Ah, Bh
#define SM_G1  (2 * STG1)              // 208896

__global__ __launch_bounds__(512, 1) void gemm_fp1(const __half* __restrict__ Ah,
                                                   const __half* __restrict__ Bh,
                                                   float* __restrict__ C,
                                                   int Kdim, int Nreal) {
    extern __shared__ char sm[];
    const int tid = threadIdx.x;
    const int lane = tid & 31, wid = tid >> 5;
    const int g = lane >> 2, q = lane & 3;
    const int wm = (wid & 3) * 32;
    const int wn = (wid >> 2) * 64;
    const int n0 = blockIdx.x * 256;
    const int m0 = blockIdx.y * 128;

    const __half* Ahb = Ah + (size_t)m0 * Kdim;
    const __half* Bhb = Bh + (size_t)n0 * Kdim;

    const uint32_t smb = smem_u32(sm);
    const uint32_t aoff = (uint32_t)((wm + (lane & 7) + ((lane >> 3) & 1) * 8) * ROWB
                                     + ((lane >> 4) & 1) * 16);
    const uint32_t boff = (uint32_t)((wn + (lane & 7) + ((lane >> 4) & 1) * 8) * ROWB
                                     + ((lane >> 3) & 1) * 16);

    float acc[2][8][4];
    #pragma unroll
    for (int mt = 0; mt < 2; mt++)
        #pragma unroll
        for (int nt = 0; nt < 8; nt++)
            #pragma unroll
            for (int i = 0; i < 4; i++) acc[mt][nt][i] = 0.f;

    const int nc = Kdim >> 7;    // BK=128 -> 8 chunks for K=1024

    auto loadStage = [&](int c, int buf) {
        const int k0 = c << 7;
        const uint32_t sb = smb + (uint32_t)(buf * STG1);
        // A: 128 rows x 16 16B-units = 2048
        #pragma unroll
        for (int i = 0; i < 4; i++) {
            int idx = tid + i * 512;
            int r = idx >> 4, u = idx & 15;
            CP_ASYNC_16(sb + (uint32_t)(r * ROWB + u * 16),
                        Ahb + (size_t)r * Kdim + k0 + u * 8);
        }
        // B: 256 rows x 16 16B-units = 4096
        #pragma unroll
        for (int i = 0; i < 8; i++) {
            int idx = tid + i * 512;
            int r = idx >> 4, u = idx & 15;
            CP_ASYNC_16(sb + (uint32_t)(ATI + r * ROWB + u * 16),
                        Bhb + (size_t)r * Kdim + k0 + u * 8);
        }
    };

    loadStage(0, 0);
    CP_ASYNC_COMMIT();

    for (int c = 0; c < nc; c++) {
        const int buf = c & 1;
        CP_ASYNC_WAIT0();
        __syncthreads();

        if (c + 1 < nc) {
            loadStage(c + 1, buf ^ 1);
            CP_ASYNC_COMMIT();
        }

        const uint32_t bb = smb + (uint32_t)(buf * STG1);
        #pragma unroll
        for (int kk = 0; kk < 8; kk++) {      // 8 k16-steps per 128-chunk
            const uint32_t kb = kk * 32;
            uint32_t ah[2][4];
            #pragma unroll
            for (int mt = 0; mt < 2; mt++)
                LDMX4(ah[mt], bb + aoff + mt * (16 * ROWB) + kb);
            #pragma unroll
            for (int p = 0; p < 4; p++) {
                uint32_t bh[4];
                LDMX4(bh, bb + ATI + boff + p * (16 * ROWB) + kb);
                #pragma unroll
                for (int s = 0; s < 2; s++) {
                    const int nt = 2 * p + s;
                    #pragma unroll
                    for (int mt = 0; mt < 2; mt++)
                        mma_fp16(acc[mt][nt], ah[mt], bh[2 * s], bh[2 * s + 1]);
                }
            }
        }
    }

    #pragma unroll
    for (int mt = 0; mt < 2; mt++) {
        #pragma unroll
        for (int nt = 0; nt < 8; nt++) {
            int row = m0 + wm + mt * 16 + g;
            int col = n0 + wn + nt * 8 + 2 * q;
            if (col < Nreal) {
                *(float2*)(C + (size_t)row * Nreal + col) =
                    make_float2(acc[mt][nt][0], acc[mt][nt][1]);
                *(float2*)(C + (size_t)(row + 8) * Nreal + col) =
                    make_float2(acc[mt][nt][2], acc[mt][nt][3]);
            }
        }
    }
}

// ---------------- causal depthwise conv + feature transform (16k blocks) ----------------
__global__ __launch_bounds__(256) void transform_kernel(const float* __restrict__ ck,
                                                        const float* __restrict__ theta,
                                                        const float* __restrict__ decay,
                                                        const float* __restrict__ anchor,
                                                        const float* __restrict__ score) {
    const int bl = blockIdx.x;
    const int l = bl & (Lv - 1);
    const int tid = threadIdx.x;
    __shared__ float pw_s[Kv];

    const size_t row = (size_t)bl * ZCv;

    if (tid < Kv) {
        int k = tid;
        int c = 2 * DIv + k;
        float s = 0.f;
        #pragma unroll
        for (int j = 0; j < CKv; j++) {
            int ll = l - (CKv - 1) + j;
            if (ll >= 0) s += ck[j * ZCv + c] * g_z[row + (long long)(ll - l) * ZCv + c];
        }
        float lw;
        if (k < Kv - Av) {
            float slope = log1pf(expf(decay[k]));
            lw = -slope * (float)(Lv - 1 - l);
        } else {
            float slope = log1pf(expf(anchor[k - (Kv - Av)]));
            lw = -slope * (float)l;
        }
        float pw = expf(score[k] * s + lw);
        pw_s[k] = pw;
        g_merged[row + k] = pw;
    }
    __syncthreads();

    for (int c = tid; c < DIv; c += 256) {
        float xv = 0.f, gv = 0.f;
        #pragma unroll
        for (int j = 0; j < CKv; j++) {
            int ll = l - (CKv - 1) + j;
            if (ll >= 0) {
                long long off = (long long)(ll - l) * ZCv;
                xv += ck[j * ZCv + c]       * g_z[row + off + c];
                gv += ck[j * ZCv + DIv + c] * g_z[row + off + DIv + c];
            }
        }
        float phi = xv * theta[c];
        float sn, cs;
        sincosf(phi, &sn, &cs);
        float pw = pw_s[c >> 5];
        g_merged[row + Kv + c]       = pw * cs;
        g_merged[row + Kv + DIv + c] = pw * sn;
        g_gate[(size_t)bl * DIv + c] = gv / (1.f + expf(-gv));
    }
}

// ---------------- segmented cumsum: partials + exclusive offsets ----------------
__global__ void scan_seg_sum() {
    int c = blockIdx.x * 256 + threadIdx.x;
    if (c >= ZCv) return;
    int seg = blockIdx.y, b = blockIdx.z;
    size_t base = ((size_t)b * Lv + (size_t)seg * SEGLEN) * ZCv + c;
    float s = 0.f;
    #pragma unroll
    for (int i = 0; i < SEGLEN; i++) s += g_merged[base + (size_t)i * ZCv];
    g_part[b][seg][c] = s;
}

__global__ void scan_offsets() {
    int c = blockIdx.x * 256 + threadIdx.x;
    if (c >= ZCv) return;
    int b = blockIdx.y;
    float run = 0.f;
    for (int s = 0; s < NSEG; s++) {
        float v = g_part[b][s][c];
        g_part[b][s][c] = run;
        run += v;
    }
}

// ---------------- blockwise cumsum-apply + normalize + mix + gate ----------------
__global__ __launch_bounds__(256) void applymix_kernel(const float* __restrict__ W_re,
                                                       const float* __restrict__ W_im,
                                                       const float* __restrict__ nscale) {
    const int b = blockIdx.x, seg = blockIdx.y;
    const int tid = threadIdx.x;
    const int lane = tid & 31;
    const int w = tid >> 5;

    __shared__ float rowv[ZCv];
    __shared__ float Wr[32][33], Wi[32][33], ns[64];
    for (int i = tid; i < 1024; i += 256) {
        Wr[i >> 5][i & 31] = W_re[i];
        Wi[i >> 5][i & 31] = W_im[i];
    }
    if (tid < 64) ns[tid] = nscale[tid];

    float carry[9];
    #pragma unroll
    for (int j = 0; j < 9; j++) {
        int c = tid + j * 256;
        carry[j] = (c < ZCv) ? g_part[b][seg][c] : 0.f;
    }
    __syncthreads();

    const size_t rowbase = ((size_t)b * Lv + (size_t)seg * SEGLEN) * ZCv;
    for (int i = 0; i < SEGLEN; i++) {
        const size_t rb = rowbase + (size_t)i * ZCv;
        #pragma unroll
        for (int j = 0; j < 9; j++) {
            int c = tid + j * 256;
            if (c < ZCv) {
                carry[j] += g_merged[rb + c];
                rowv[c] = carry[j];
            }
        }
        __syncthreads();

        const int bl = b * Lv + seg * SEGLEN + i;
        #pragma unroll
        for (int kk = 0; kk < 4; kk++) {
            int k = w * 4 + kk;
            float inv = 1.f / fmaxf(rowv[k], 1e-4f);
            float re = rowv[Kv + k * 32 + lane] * inv;
            float im = rowv[Kv + DIv + k * 32 + lane] * inv;
            float ss = re * re + im * im;
            #pragma unroll
            for (int o = 16; o > 0; o >>= 1) ss += __shfl_xor_sync(0xffffffffu, ss, o);
            float rs = rsqrtf(ss * (1.f / 64.f) + 1e-5f);
            float a  = re * rs * ns[lane];
            float bb = im * rs * ns[32 + lane];
            float ya = 0.f, yb = 0.f;          // two independent FMA chains
            #pragma unroll
            for (int h = 0; h < 32; h++) {
                ya = fmaf(__shfl_sync(0xffffffffu, a,  h), Wr[h][lane], ya);
                yb = fmaf(__shfl_sync(0xffffffffu, bb, h), Wi[h][lane], yb);
            }
            size_t gi = (size_t)bl * DIv + k * 32 + lane;
            g_hh[gi] = __float2half_rn((ya + yb) * g_gate[gi]);
        }
        __syncthreads();
    }
}

// ---------------- launch ----------------
extern "C" void kernel_launch(void* const* d_in, const int* in_sizes, int n_in,
                              void* d_out, int out_size) {
    const float* x      = (const float*)d_in[0];   // [4,4096,1024]
    const float* W_in   = (const float*)d_in[1];   // [1024,2080]
    const float* convk  = (const float*)d_in[2];   // [4,1,2080]
    const float* theta  = (const float*)d_in[3];   // [1024]
    const float* decay  = (const float*)d_in[4];   // [28]
    const float* anchor = (const float*)d_in[5];   // [4]
    const float* score  = (const float*)d_in[6];   // [32]
    const float* W_re   = (const float*)d_in[7];   // [32,32]
    const float* W_im   = (const float*)d_in[8];   // [32,32]
    const float* nscale = (const float*)d_in[9];   // [64]
    const float* W_out  = (const float*)d_in[10];  // [1024,1024]
    float* out = (float*)d_out;                    // [4,4096,1024]

    float* zbuf; cudaGetSymbolAddress((void**)&zbuf, g_z);
    __half *ch1, *ch2, *xh, *hh;
    cudaGetSymbolAddress((void**)&ch1, g_ch1);
    cudaGetSymbolAddress((void**)&ch2, g_ch2);
    cudaGetSymbolAddress((void**)&xh, g_xh);
    cudaGetSymbolAddress((void**)&hh, g_hh);

    cudaFuncSetAttribute(gemm_fp1, cudaFuncAttributeMaxDynamicSharedMemorySize, SM_G1);

    // (0,1) weight transpose -> fp16
    {
        dim3 blk(32, 8);
        prep_h<<<dim3(NPAD1 / 32, Dv / 32), blk>>>(W_in, ch1, Dv, ZCv);
        prep_h<<<dim3(Dv / 32, Dv / 32),   blk>>>(W_out, ch2, Dv, Dv);
    }
    // (2) x -> fp16
    split_x<<<(BLv * Dv) / (256 * 4), 256>>>(x);
    // (3) z = x @ W_in   (plain fp16, BK=128)
    {
        dim3 grid(NPAD1 / 256, BLv / 128);
        gemm_fp1<<<grid, 512, SM_G1>>>(xh, ch1, zbuf, Dv, ZCv);
    }
    // (4) conv + features (16k blocks)
    transform_kernel<<<BLv, 256>>>(convk, theta, decay, anchor, score);
    // (5,6) segment partials + exclusive offsets
    {
        dim3 g1((ZCv + 255) / 256, NSEG, Bv);
        scan_seg_sum<<<g1, 256>>>();
        dim3 g2((ZCv + 255) / 256, Bv);
        scan_offsets<<<g2, 256>>>();
    }
    // (7) blockwise applymix (split accumulator chains)
    {
        dim3 grid(Bv, NSEG);
        applymix_kernel<<<grid, 256>>>(W_re, W_im, nscale);
    }
    // (8) out = h @ W_out  (plain fp16, BK=128)
    {
        dim3 grid(Dv / 256, BLv / 128);
        gemm_fp1<<<grid, 512, SM_G1>>>(hh, ch2, out, Dv, Dv);
    }
}

// round 17
// speedup vs baseline: 1.0290x; 1.0290x over previous
#include <cuda_runtime.h>
#include <cuda_bf16.h>
#include <cuda_fp16.h>
#include <math.h>
#include <stdint.h>

// ---------------- static config ----------------
#define Bv 4
#define Lv 4096
#define Dv 1024
#define Kv 32
#define Hv 32
#define Av 4
#define CKv 4
#define DIv 1024          // d_inner
#define ZCv 2080          // 2*DI + K
#define BLv (Bv*Lv)       // 16384
#define NPAD1 2304        // 9 * 256 (padded N for GEMM1, N-tile 256)

#define NSEG 512
#define SEGLEN (Lv/NSEG)  // 8

// ---------------- scratch (device globals; no allocation) ----------------
__device__ float g_z[(size_t)BLv * ZCv];        // in_proj output
__device__ float g_merged[(size_t)BLv * ZCv];   // [den|re|im] features
__device__ float g_gate[(size_t)BLv * DIv];     // silu gate
__device__ __half g_hh[(size_t)BLv * DIv];      // y * gate (fp16, GEMM2 A)
__device__ float g_part[Bv][NSEG][ZCv];         // segment partial sums
// fp16 activations for GEMM1
__device__ __half g_xh[(size_t)BLv * Dv];
// transposed fp16 weights, K-major (single-rounded; 1-term GEMM)
__device__ __half g_ch1[(size_t)NPAD1 * Dv];    // W_in
__device__ __half g_ch2[(size_t)Dv * Dv];       // W_out

// ---------------- helpers ----------------
__device__ __forceinline__ uint32_t smem_u32(const void* p) {
    uint32_t a;
    asm("{ .reg .u64 t; cvta.to.shared.u64 t, %1; cvt.u32.u64 %0, t; }" : "=r"(a) : "l"(p));
    return a;
}
#define CP_ASYNC_16(dst_u32, src_ptr) \
    asm volatile("cp.async.cg.shared.global [%0], [%1], 16;" :: "r"(dst_u32), "l"(src_ptr))
#define CP_ASYNC_COMMIT() asm volatile("cp.async.commit_group;" ::: "memory")
#define CP_ASYNC_WAIT0()  asm volatile("cp.async.wait_group 0;" ::: "memory")

#define LDMX4(r, addr) \
    asm volatile("ldmatrix.sync.aligned.m8n8.x4.shared.b16 {%0,%1,%2,%3}, [%4];" \
        : "=r"((r)[0]), "=r"((r)[1]), "=r"((r)[2]), "=r"((r)[3]) : "r"(addr))

__device__ __forceinline__ void mma_fp16(float c[4], const uint32_t a[4],
                                         uint32_t b0, uint32_t b1) {
    asm volatile(
        "mma.sync.aligned.m16n8k16.row.col.f32.f16.f16.f32 "
        "{%0,%1,%2,%3}, {%4,%5,%6,%7}, {%8,%9}, {%0,%1,%2,%3};"
        : "+f"(c[0]), "+f"(c[1]), "+f"(c[2]), "+f"(c[3])
        : "r"(a[0]), "r"(a[1]), "r"(a[2]), "r"(a[3]), "r"(b0), "r"(b1));
}

// ---------------- weight transpose (fp16, single-rounded) ----------------
__global__ void prep_h(const float* __restrict__ W,
                       __half* __restrict__ Bh,
                       int Kdim, int Nreal) {
    __shared__ float t[32][33];
    const int nb = blockIdx.x * 32, kb = blockIdx.y * 32;
    const int tx = threadIdx.x, ty = threadIdx.y;   // 32 x 8
    #pragma unroll
    for (int j = 0; j < 4; j++) {
        int k = kb + ty + j * 8, n = nb + tx;
        t[ty + j * 8][tx] = (n < Nreal) ? W[(size_t)k * Nreal + n] : 0.f;
    }
    __syncthreads();
    #pragma unroll
    for (int j = 0; j < 4; j++) {
        int n = nb + ty + j * 8, k = kb + tx;
        Bh[(size_t)n * Kdim + k] = __float2half_rn(t[tx][ty + j * 8]);
    }
}

// ---------------- x fp32 -> fp16 (single-rounded) ----------------
__global__ __launch_bounds__(256) void split_x(const float* __restrict__ x) {
    size_t i = ((size_t)blockIdx.x * 256 + threadIdx.x) * 4;
    float4 v = *(const float4*)(x + i);
    uint32_t hh[2];
    hh[0] = (uint32_t)__half_as_ushort(__float2half_rn(v.x))
          | ((uint32_t)__half_as_ushort(__float2half_rn(v.y)) << 16);
    hh[1] = (uint32_t)__half_as_ushort(__float2half_rn(v.z))
          | ((uint32_t)__half_as_ushort(__float2half_rn(v.w)) << 16);
    *(uint2*)(g_xh + i) = make_uint2(hh[0], hh[1]);
}

// ---------------- GEMM (1-term fp16; 512 thr, warp 32x64, BK=64) ----------------
#define ROWB   144
#define ATI    (128 * ROWB)            // 18432
#define BTI    (256 * ROWB)            // 36864
#define STG1   (ATI + BTI)             // 55296: Ah, Bh
#define SM_G1  (2 * STG1)              // 110592

__global__ __launch_bounds__(512, 1) void gemm_fp1(const __half* __restrict__ Ah,
                                                   const __half* __restrict__ Bh,
                                                   float* __restrict__ C,
                                                   int Kdim, int Nreal) {
    extern __shared__ char sm[];
    const int tid = threadIdx.x;
    const int lane = tid & 31, wid = tid >> 5;
    const int g = lane >> 2, q = lane & 3;
    const int wm = (wid & 3) * 32;
    const int wn = (wid >> 2) * 64;
    const int n0 = blockIdx.x * 256;
    const int m0 = blockIdx.y * 128;

    const __half* Ahb = Ah + (size_t)m0 * Kdim;
    const __half* Bhb = Bh + (size_t)n0 * Kdim;

    const uint32_t smb = smem_u32(sm);
    const uint32_t aoff = (uint32_t)((wm + (lane & 7) + ((lane >> 3) & 1) * 8) * ROWB
                                     + ((lane >> 4) & 1) * 16);
    const uint32_t boff = (uint32_t)((wn + (lane & 7) + ((lane >> 4) & 1) * 8) * ROWB
                                     + ((lane >> 3) & 1) * 16);

    float acc[2][8][4];
    #pragma unroll
    for (int mt = 0; mt < 2; mt++)
        #pragma unroll
        for (int nt = 0; nt < 8; nt++)
            #pragma unroll
            for (int i = 0; i < 4; i++) acc[mt][nt][i] = 0.f;

    const int nc = Kdim >> 6;    // BK=64

    auto loadStage = [&](int c, int buf) {
        const int k0 = c << 6;
        const uint32_t sb = smb + (uint32_t)(buf * STG1);
        #pragma unroll
        for (int i = 0; i < 2; i++) {
            int idx = tid + i * 512;
            int r = idx >> 3, u = idx & 7;
            CP_ASYNC_16(sb + (uint32_t)(r * ROWB + u * 16),
                        Ahb + (size_t)r * Kdim + k0 + u * 8);
        }
        #pragma unroll
        for (int i = 0; i < 4; i++) {
            int idx = tid + i * 512;
            int r = idx >> 3, u = idx & 7;
            CP_ASYNC_16(sb + (uint32_t)(ATI + r * ROWB + u * 16),
                        Bhb + (size_t)r * Kdim + k0 + u * 8);
        }
    };

    loadStage(0, 0);
    CP_ASYNC_COMMIT();

    for (int c = 0; c < nc; c++) {
        const int buf = c & 1;
        CP_ASYNC_WAIT0();
        __syncthreads();

        if (c + 1 < nc) {
            loadStage(c + 1, buf ^ 1);
            CP_ASYNC_COMMIT();
        }

        const uint32_t bb = smb + (uint32_t)(buf * STG1);
        #pragma unroll
        for (int kk = 0; kk < 4; kk++) {
            const uint32_t kb = kk * 32;
            uint32_t ah[2][4];
            #pragma unroll
            for (int mt = 0; mt < 2; mt++)
                LDMX4(ah[mt], bb + aoff + mt * (16 * ROWB) + kb);
            #pragma unroll
            for (int p = 0; p < 4; p++) {
                uint32_t bh[4];
                LDMX4(bh, bb + ATI + boff + p * (16 * ROWB) + kb);
                #pragma unroll
                for (int s = 0; s < 2; s++) {
                    const int nt = 2 * p + s;
                    #pragma unroll
                    for (int mt = 0; mt < 2; mt++)
                        mma_fp16(acc[mt][nt], ah[mt], bh[2 * s], bh[2 * s + 1]);
                }
            }
        }
    }

    #pragma unroll
    for (int mt = 0; mt < 2; mt++) {
        #pragma unroll
        for (int nt = 0; nt < 8; nt++) {
            int row = m0 + wm + mt * 16 + g;
            int col = n0 + wn + nt * 8 + 2 * q;
            if (col < Nreal) {
                *(float2*)(C + (size_t)row * Nreal + col) =
                    make_float2(acc[mt][nt][0], acc[mt][nt][1]);
                *(float2*)(C + (size_t)(row + 8) * Nreal + col) =
                    make_float2(acc[mt][nt][2], acc[mt][nt][3]);
            }
        }
    }
}

// ---------------- causal depthwise conv + feature transform (16k blocks) ----------------
__global__ __launch_bounds__(256) void transform_kernel(const float* __restrict__ ck,
                                                        const float* __restrict__ theta,
                                                        const float* __restrict__ decay,
                                                        const float* __restrict__ anchor,
                                                        const float* __restrict__ score) {
    const int bl = blockIdx.x;
    const int l = bl & (Lv - 1);
    const int tid = threadIdx.x;
    __shared__ float pw_s[Kv];

    const size_t row = (size_t)bl * ZCv;

    if (tid < Kv) {
        int k = tid;
        int c = 2 * DIv + k;
        float s = 0.f;
        #pragma unroll
        for (int j = 0; j < CKv; j++) {
            int ll = l - (CKv - 1) + j;
            if (ll >= 0) s += ck[j * ZCv + c] * g_z[row + (long long)(ll - l) * ZCv + c];
        }
        float lw;
        if (k < Kv - Av) {
            float slope = log1pf(expf(decay[k]));
            lw = -slope * (float)(Lv - 1 - l);
        } else {
            float slope = log1pf(expf(anchor[k - (Kv - Av)]));
            lw = -slope * (float)l;
        }
        float pw = expf(score[k] * s + lw);
        pw_s[k] = pw;
        g_merged[row + k] = pw;
    }
    __syncthreads();

    for (int c = tid; c < DIv; c += 256) {
        float xv = 0.f, gv = 0.f;
        #pragma unroll
        for (int j = 0; j < CKv; j++) {
            int ll = l - (CKv - 1) + j;
            if (ll >= 0) {
                long long off = (long long)(ll - l) * ZCv;
                xv += ck[j * ZCv + c]       * g_z[row + off + c];
                gv += ck[j * ZCv + DIv + c] * g_z[row + off + DIv + c];
            }
        }
        float phi = xv * theta[c];
        float sn, cs;
        sincosf(phi, &sn, &cs);
        float pw = pw_s[c >> 5];
        g_merged[row + Kv + c]       = pw * cs;
        g_merged[row + Kv + DIv + c] = pw * sn;
        g_gate[(size_t)bl * DIv + c] = gv / (1.f + expf(-gv));
    }
}

// ---------------- segmented cumsum: partials + exclusive offsets ----------------
__global__ void scan_seg_sum() {
    int c = blockIdx.x * 256 + threadIdx.x;
    if (c >= ZCv) return;
    int seg = blockIdx.y, b = blockIdx.z;
    size_t base = ((size_t)b * Lv + (size_t)seg * SEGLEN) * ZCv + c;
    float s = 0.f;
    #pragma unroll
    for (int i = 0; i < SEGLEN; i++) s += g_merged[base + (size_t)i * ZCv];
    g_part[b][seg][c] = s;
}

__global__ void scan_offsets() {
    int c = blockIdx.x * 256 + threadIdx.x;
    if (c >= ZCv) return;
    int b = blockIdx.y;
    float run = 0.f;
    for (int s = 0; s < NSEG; s++) {
        float v = g_part[b][s][c];
        g_part[b][s][c] = run;
        run += v;
    }
}

// ---------------- blockwise cumsum-apply + normalize + mix + gate ----------------
// Mix inner loop: pack (a,b) as half2, ONE shfl per h, unpack to fp32, 2 FMA.
__global__ __launch_bounds__(256) void applymix_kernel(const float* __restrict__ W_re,
                                                       const float* __restrict__ W_im,
                                                       const float* __restrict__ nscale) {
    const int b = blockIdx.x, seg = blockIdx.y;
    const int tid = threadIdx.x;
    const int lane = tid & 31;
    const int w = tid >> 5;

    __shared__ float rowv[ZCv];
    __shared__ float Wr[32][33], Wi[32][33], ns[64];
    for (int i = tid; i < 1024; i += 256) {
        Wr[i >> 5][i & 31] = W_re[i];
        Wi[i >> 5][i & 31] = W_im[i];
    }
    if (tid < 64) ns[tid] = nscale[tid];

    float carry[9];
    #pragma unroll
    for (int j = 0; j < 9; j++) {
        int c = tid + j * 256;
        carry[j] = (c < ZCv) ? g_part[b][seg][c] : 0.f;
    }
    __syncthreads();

    const size_t rowbase = ((size_t)b * Lv + (size_t)seg * SEGLEN) * ZCv;
    for (int i = 0; i < SEGLEN; i++) {
        const size_t rb = rowbase + (size_t)i * ZCv;
        #pragma unroll
        for (int j = 0; j < 9; j++) {
            int c = tid + j * 256;
            if (c < ZCv) {
                carry[j] += g_merged[rb + c];
                rowv[c] = carry[j];
            }
        }
        __syncthreads();

        const int bl = b * Lv + seg * SEGLEN + i;
        #pragma unroll
        for (int kk = 0; kk < 4; kk++) {
            int k = w * 4 + kk;
            float inv = 1.f / fmaxf(rowv[k], 1e-4f);
            float re = rowv[Kv + k * 32 + lane] * inv;
            float im = rowv[Kv + DIv + k * 32 + lane] * inv;
            float ss = re * re + im * im;
            #pragma unroll
            for (int o = 16; o > 0; o >>= 1) ss += __shfl_xor_sync(0xffffffffu, ss, o);
            float rs = rsqrtf(ss * (1.f / 64.f) + 1e-5f);
            float a  = re * rs * ns[lane];
            float bb = im * rs * ns[32 + lane];
            // pack normalized (a,b) -> half2; one shfl per h
            __half2 p2 = __floats2half2_rn(a, bb);
            uint32_t pk = *(uint32_t*)&p2;
            float y = 0.f;
            #pragma unroll
            for (int h = 0; h < 32; h++) {
                uint32_t v = __shfl_sync(0xffffffffu, pk, h);
                float2 ab = __half22float2(*(__half2*)&v);
                y = fmaf(ab.x, Wr[h][lane], y);
                y = fmaf(ab.y, Wi[h][lane], y);
            }
            size_t gi = (size_t)bl * DIv + k * 32 + lane;
            g_hh[gi] = __float2half_rn(y * g_gate[gi]);
        }
        __syncthreads();
    }
}

// ---------------- launch ----------------
extern "C" void kernel_launch(void* const* d_in, const int* in_sizes, int n_in,
                              void* d_out, int out_size) {
    const float* x      = (const float*)d_in[0];   // [4,4096,1024]
    const float* W_in   = (const float*)d_in[1];   // [1024,2080]
    const float* convk  = (const float*)d_in[2];   // [4,1,2080]
    const float* theta  = (const float*)d_in[3];   // [1024]
    const float* decay  = (const float*)d_in[4];   // [28]
    const float* anchor = (const float*)d_in[5];   // [4]
    const float* score  = (const float*)d_in[6];   // [32]
    const float* W_re   = (const float*)d_in[7];   // [32,32]
    const float* W_im   = (const float*)d_in[8];   // [32,32]
    const float* nscale = (const float*)d_in[9];   // [64]
    const float* W_out  = (const float*)d_in[10];  // [1024,1024]
    float* out = (float*)d_out;                    // [4,4096,1024]

    float* zbuf; cudaGetSymbolAddress((void**)&zbuf, g_z);
    __half *ch1, *ch2, *xh, *hh;
    cudaGetSymbolAddress((void**)&ch1, g_ch1);
    cudaGetSymbolAddress((void**)&ch2, g_ch2);
    cudaGetSymbolAddress((void**)&xh, g_xh);
    cudaGetSymbolAddress((void**)&hh, g_hh);

    cudaFuncSetAttribute(gemm_fp1, cudaFuncAttributeMaxDynamicSharedMemorySize, SM_G1);

    // (0,1) weight transpose -> fp16
    {
        dim3 blk(32, 8);
        prep_h<<<dim3(NPAD1 / 32, Dv / 32), blk>>>(W_in, ch1, Dv, ZCv);
        prep_h<<<dim3(Dv / 32, Dv / 32),   blk>>>(W_out, ch2, Dv, Dv);
    }
    // (2) x -> fp16
    split_x<<<(BLv * Dv) / (256 * 4), 256>>>(x);
    // (3) z = x @ W_in   (plain fp16, BK=64)
    {
        dim3 grid(NPAD1 / 256, BLv / 128);
        gemm_fp1<<<grid, 512, SM_G1>>>(xh, ch1, zbuf, Dv, ZCv);
    }
    // (4) conv + features (16k blocks)
    transform_kernel<<<BLv, 256>>>(convk, theta, decay, anchor, score);
    // (5,6) segment partials + exclusive offsets
    {
        dim3 g1((ZCv + 255) / 256, NSEG, Bv);
        scan_seg_sum<<<g1, 256>>>();
        dim3 g2((ZCv + 255) / 256, Bv);
        scan_offsets<<<g2, 256>>>();
    }
    // (7) blockwise applymix (packed half2 shfl)
    {
        dim3 grid(Bv, NSEG);
        applymix_kernel<<<grid, 256>>>(W_re, W_im, nscale);
    }
    // (8) out = h @ W_out  (plain fp16, BK=64)
    {
        dim3 grid(Dv / 256, BLv / 128);
        gemm_fp1<<<grid, 512, SM_G1>>>(hh, ch2, out, Dv, Dv);
    }
}